// round 12
// baseline (speedup 1.0000x reference)
#include <cuda_runtime.h>

#define NV   2000000
#define NC   2000
#define NE   16000
#define NREP 16        // replicas per cluster, padded to 32B stride
#define GRID 296       // 2 CTAs/SM x 148 SMs: all blocks co-resident
#define TPB  512
#define MLPB (NE / 128)  // 125 MLP blocks, 128 edges each

// Scratch (no cudaMalloc allowed).
// Replica r of cluster c at float4 index c*32 + r*2 (32B apart: own L2 sector).
__device__ float4       g_rsum[NC * NREP * 2];
__device__ unsigned int g_icnt[NC];
// Monotonic grid-barrier counters (never reset; grow by GRID per launch).
__device__ unsigned int g_bar0, g_bar1;

__device__ __forceinline__ void red_v4(float4* a, float x, float y, float z, float w) {
    asm volatile("red.global.add.v4.f32 [%0], {%1,%2,%3,%4};"
                 :: "l"(a), "f"(x), "f"(y), "f"(z), "f"(w) : "memory");
}
__device__ __forceinline__ void red_u32(unsigned int* a, unsigned int v) {
    asm volatile("red.global.add.u32 [%0], %1;" :: "l"(a), "r"(v) : "memory");
}
__device__ __forceinline__ unsigned long long pack2(float a, float b) {
    unsigned long long r;
    asm("mov.b64 %0, {%1, %2};" : "=l"(r) : "f"(a), "f"(b));
    return r;
}
__device__ __forceinline__ void unpack2(unsigned long long v, float& a, float& b) {
    asm("mov.b64 {%0, %1}, %2;" : "=f"(a), "=f"(b) : "l"(v));
}
__device__ __forceinline__ void ffma2(unsigned long long& d,
                                      unsigned long long a, unsigned long long b) {
    asm("fma.rn.f32x2 %0, %1, %2, %0;" : "+l"(d) : "l"(a), "l"(b));
}

// Software grid barrier: monotonic counter, wrap-free across graph replays.
// All GRID blocks are co-resident (2 CTAs/SM @ 104KB smem), so spinning is safe.
__device__ __forceinline__ void grid_barrier(unsigned int* ctr) {
    __syncthreads();
    if (threadIdx.x == 0) {
        __threadfence();
        unsigned int t = atomicAdd(ctr, 1u);
        unsigned int target = (t / GRID + 1u) * GRID;
        unsigned int v;
        do {
            asm volatile("ld.acquire.gpu.u32 %0, [%1];" : "=r"(v) : "l"(ctr));
        } while (v < target);
        __threadfence();
    }
    __syncthreads();
}

// ---------------------------------------------------------------------------
// ONE fused kernel, 296 x 512.
// Phase 0: zero accumulators, preload W2, zero smem hist.
// Phase 1: segment sum (red.v4 replicas + smem count hist), all 512 threads.
// Phase 2: blocks 0..124 run the MLP on 128 edges each.
// smem floats: W2 [0,8192) | h [8192,24576) ([128][128]) | misc [24576,26624)
// ---------------------------------------------------------------------------
__global__ __launch_bounds__(TPB) void k_fused(const float* __restrict__ data,
                                               const int*   __restrict__ cid,
                                               const int*   __restrict__ eidx,
                                               const float* __restrict__ W1,
                                               const float* __restrict__ b1,
                                               const float* __restrict__ W2,
                                               const float* __restrict__ b2,
                                               float*       __restrict__ out) {
    extern __shared__ float sm[];
    float* s_W2   = sm;                      // 8192 floats [128][64]
    float* s_h    = sm + 8192;               // 16384 floats [128][128] k-major
    float* s_misc = sm + 24576;              // 2048 floats

    const int t   = threadIdx.x;
    const int bid = blockIdx.x;

    // ---- Phase 0 ----
    for (int i = bid * TPB + t; i < NC * NREP * 2; i += GRID * TPB)
        g_rsum[i] = make_float4(0.f, 0.f, 0.f, 0.f);
    for (int i = bid * TPB + t; i < NC; i += GRID * TPB)
        g_icnt[i] = 0u;
    for (int i = t; i < 8192 / 4; i += TPB)
        ((float4*)s_W2)[i] = ((const float4*)W2)[i];
    unsigned int* s_cnt = (unsigned int*)s_misc;   // 8KB histogram
    for (int i = t; i < NC; i += TPB) s_cnt[i] = 0u;

    grid_barrier(&g_bar0);

    // ---- Phase 1: segment sum ----
    {
        const int rep2 = ((bid * 16 + (t >> 5)) & (NREP - 1)) * 2;
        const int NG = NV / 4;
        const int stride = GRID * TPB;
#pragma unroll 2
        for (int g = bid * TPB + t; g < NG; g += stride) {
            const float4* p = (const float4*)data + (size_t)g * 5;
            float4 q0 = __ldg(p + 0);
            float4 q1 = __ldg(p + 1);
            float4 q2 = __ldg(p + 2);
            float4 q3 = __ldg(p + 3);
            float4 q4 = __ldg(p + 4);
            int4 c = __ldg((const int4*)cid + g);

            // voxel layout: [d f0 f1 f2 f3] x4 -> features are cols 1..4
            red_v4(&g_rsum[c.x * (NREP * 2) + rep2], q0.y, q0.z, q0.w, q1.x);
            red_v4(&g_rsum[c.y * (NREP * 2) + rep2], q1.z, q1.w, q2.x, q2.y);
            red_v4(&g_rsum[c.z * (NREP * 2) + rep2], q2.w, q3.x, q3.y, q3.z);
            red_v4(&g_rsum[c.w * (NREP * 2) + rep2], q4.x, q4.y, q4.z, q4.w);

            atomicAdd(&s_cnt[c.x], 1u);
            atomicAdd(&s_cnt[c.y], 1u);
            atomicAdd(&s_cnt[c.z], 1u);
            atomicAdd(&s_cnt[c.w], 1u);
        }
        __syncthreads();
        for (int i = t; i < NC; i += TPB) {
            unsigned int v = s_cnt[i];
            if (v) red_u32(&g_icnt[i], v);
        }
    }

    grid_barrier(&g_bar1);

    // ---- Phase 2: MLP, blocks 0..124, 128 edges each ----
    if (bid >= MLPB) return;

    float* s_W1   = s_misc;          // 512 floats [4][128]  (hist is dead)
    float* s_b1   = s_misc + 512;    // 128
    float* s_b2   = s_misc + 640;    // 64
    float* s_pool = s_misc + 704;    // 640 floats [128][5]

    __syncthreads();
    if (t < 128) ((float4*)s_W1)[t] = ((const float4*)W1)[t];
    if (t < 128) s_b1[t] = b1[t];
    if (t < 64)  s_b2[t] = b2[t];

    const int base = bid * 128;

    // Gather: 4 threads/edge (q = t&3), each sums 4 padded replicas of both
    // endpoints (8 pipelined LDG.128 from warm L2), 2-step shfl reduce.
    {
        int q = t & 3;
        int e = t >> 2;                       // 0..127
        int eg = base + e;
        int a = __ldg(eidx + eg);
        int b = __ldg(eidx + NE + eg);

        const float4* ra = g_rsum + a * (NREP * 2) + q * 8;
        const float4* rb = g_rsum + b * (NREP * 2) + q * 8;
        float4 s = make_float4(0.f, 0.f, 0.f, 0.f);
#pragma unroll
        for (int r = 0; r < 4; r++) {
            float4 va = __ldg(ra + r * 2);
            float4 vb = __ldg(rb + r * 2);
            s.x += va.x + vb.x;
            s.y += va.y + vb.y;
            s.z += va.z + vb.z;
            s.w += va.w + vb.w;
        }
#pragma unroll
        for (int off = 2; off > 0; off >>= 1) {
            s.x += __shfl_down_sync(0xffffffff, s.x, off);
            s.y += __shfl_down_sync(0xffffffff, s.y, off);
            s.z += __shfl_down_sync(0xffffffff, s.z, off);
            s.w += __shfl_down_sync(0xffffffff, s.w, off);
        }
        if (q == 0) {
            float cnt = (float)(__ldg(g_icnt + a) + __ldg(g_icnt + b));
            float inv = 1.f / fmaxf(cnt, 1.f);
            s_pool[e * 5 + 0] = s.x * inv;
            s_pool[e * 5 + 1] = s.y * inv;
            s_pool[e * 5 + 2] = s.z * inv;
            s_pool[e * 5 + 3] = s.w * inv;
        }
    }
    __syncthreads();

    // Phase A: e = t&127, k-group kq = (t>>7)*32 (4 groups x 32 k).
    {
        int e  = t & 127;
        int kq = (t >> 7) * 32;
        float p0 = s_pool[e * 5 + 0];
        float p1 = s_pool[e * 5 + 1];
        float p2 = s_pool[e * 5 + 2];
        float p3 = s_pool[e * 5 + 3];
#pragma unroll 4
        for (int j = 0; j < 32; j++) {
            int k = kq + j;
            float h = s_b1[k]
                    + p0 * s_W1[0 * 128 + k]
                    + p1 * s_W1[1 * 128 + k]
                    + p2 * s_W1[2 * 128 + k]
                    + p3 * s_W1[3 * 128 + k];
            s_h[k * 128 + e] = fmaxf(h, 0.f);
        }
    }
    __syncthreads();

    // Phase B: tx = out quad (16), ty = edge quad (32). 4 edges x 4 outs/thread.
    const int tx = t & 15;
    const int ty = t >> 4;
    unsigned long long acc[4][2];
#pragma unroll
    for (int i = 0; i < 4; i++) { acc[i][0] = 0ull; acc[i][1] = 0ull; }

    const float4* hf4 = (const float4*)s_h;    // [128][32] quads
    const float4* wf4 = (const float4*)s_W2;   // [128][16] quads
#pragma unroll 4
    for (int k = 0; k < 128; k++) {
        float4 w = wf4[k * 16 + tx];           // conflict-free
        float4 h = hf4[k * 32 + ty];           // broadcast pairs
        unsigned long long w01 = pack2(w.x, w.y);
        unsigned long long w23 = pack2(w.z, w.w);
        float hv[4] = {h.x, h.y, h.z, h.w};
#pragma unroll
        for (int i = 0; i < 4; i++) {
            unsigned long long hh = pack2(hv[i], hv[i]);
            ffma2(acc[i][0], hh, w01);
            ffma2(acc[i][1], hh, w23);
        }
    }

    float c0 = s_b2[tx * 4 + 0];
    float c1 = s_b2[tx * 4 + 1];
    float c2 = s_b2[tx * 4 + 2];
    float c3 = s_b2[tx * 4 + 3];
#pragma unroll
    for (int i = 0; i < 4; i++) {
        int e = base + ty * 4 + i;
        float a0, a1, a2, a3;
        unpack2(acc[i][0], a0, a1);
        unpack2(acc[i][1], a2, a3);
        float4 o = make_float4(a0 + c0, a1 + c1, a2 + c2, a3 + c3);
        ((float4*)out)[e * 16 + tx] = o;
    }
}

// ---------------------------------------------------------------------------
// Launch: ONE kernel node (graph-capturable)
// ---------------------------------------------------------------------------
extern "C" void kernel_launch(void* const* d_in, const int* in_sizes, int n_in,
                              void* d_out, int out_size) {
    const float* data = (const float*)d_in[0];
    const int*   cid  = (const int*)  d_in[1];
    const int*   eidx = (const int*)  d_in[2];
    const float* W1   = (const float*)d_in[3];
    const float* b1   = (const float*)d_in[4];
    const float* W2   = (const float*)d_in[5];
    const float* b2   = (const float*)d_in[6];
    float*       out  = (float*)d_out;

    cudaFuncSetAttribute(k_fused, cudaFuncAttributeMaxDynamicSharedMemorySize, 106496);

    k_fused<<<GRID, TPB, 106496>>>(data, cid, eidx, W1, b1, W2, b2, out);
}